// round 15
// baseline (speedup 1.0000x reference)
#include <cuda_runtime.h>
#include <cuda_bf16.h>
#include <math.h>
#include <stdint.h>

#define NN 50000
#define NE 800000
#define EP (NE + NN)   // edges + self loops
#define FD 128

#define HIST_BLOCKS ((NE + 255) / 256)   // 3125
#define PREP_BLOCKS 48
#define GEMM_BX     ((NN + 127) / 128)   // 391

typedef uint32_t u32;

// -------------------- device scratch (no allocs allowed) --------------------
__device__ float g_Q[NN * FD];
__device__ float g_K[NN * FD];
__device__ float g_V[NN * FD];
__device__ int   g_cnt[NN];      // zeroed at load; re-zeroed by aggregate each replay
__device__ int   g_off[NN + 1];
__device__ int   g_cur[NN];
__device__ int   g_scol[EP];
// W transposed (N-major), 2-level int8: [mat][level][n=128][kquad=32] u32 (4 s8 each)
__device__ u32   g_W8[3 * 2 * 128 * 32];

__device__ __forceinline__ u32 smem_u32(const void* p) {
    u32 a; asm("{ .reg .u64 t; cvta.to.shared.u64 t, %1; cvt.u32.u64 %0, t; }"
               : "=r"(a) : "l"(p));
    return a;
}

// -------------------- int8 two-level quant helpers --------------------
// x = 2^-4 * (X0 + X1/256) ; w = 2^-8 * (W0 + W1/256)
__device__ __forceinline__ void quant2(float v, float inv0, float s0, int& q0, int& q1) {
    q0 = __float2int_rn(v * inv0);
    float r = v - (float)q0 * s0;
    int t = __float2int_rn(r * inv0 * 256.f);
    q1 = t > 127 ? 127 : (t < -127 ? -127 : t);
}
__device__ __forceinline__ u32 pack4(int a, int b, int c, int d) {
    return (u32)(a & 255) | ((u32)(b & 255) << 8) |
           ((u32)(c & 255) << 16) | ((u32)(d & 255) << 24);
}

// -------------------- sort chain (secondary stream) --------------------
__global__ void hist_kernel(const int* __restrict__ ei) {
    int e = blockIdx.x * blockDim.x + threadIdx.x;
    if (e < NE) atomicAdd(&g_cnt[ei[e]], 1);   // target = ei[0][e]
}

// exclusive scan over (g_cnt[i] + 1); +1 = implicit self loop
__global__ __launch_bounds__(1024) void scan_kernel() {
    __shared__ int sums[1024];
    const int t = threadIdx.x;
    const int CH = (NN + 1023) / 1024;   // 49
    int start = t * CH;
    int end   = start + CH; if (end > NN) end = NN;

    int s = 0;
    for (int i = start; i < end; i++) s += g_cnt[i] + 1;
    sums[t] = s;
    __syncthreads();
    for (int d = 1; d < 1024; d <<= 1) {
        int v = (t >= d) ? sums[t - d] : 0;
        __syncthreads();
        sums[t] += v;
        __syncthreads();
    }
    int run = sums[t] - s;
    for (int i = start; i < end; i++) {
        g_off[i] = run;
        g_cur[i] = run;
        run += g_cnt[i] + 1;
    }
    if (start < NN && end == NN) g_off[NN] = run;
}

__global__ void scatter_kernel(const int* __restrict__ ei) {
    int e = blockIdx.x * blockDim.x + threadIdx.x;
    if (e >= EP) return;
    int rr, cc;
    if (e < NE) { rr = ei[e]; cc = ei[NE + e]; }
    else        { rr = e - NE; cc = rr; }          // self loop
    int pos = atomicAdd(&g_cur[rr], 1);
    g_scol[pos] = cc;
}

// -------------------- W prep: transpose + 2-level int8 quantize --------------
__global__ __launch_bounds__(256) void prep_kernel(
    const float* __restrict__ Wq, const float* __restrict__ Wk,
    const float* __restrict__ Wv)
{
    int P = blockIdx.x * 256 + threadIdx.x;   // 0..12287 = (mat, kq, n)
    int mat = P >> 12;
    int rem = P & 4095;
    int kq  = rem >> 7;
    int n   = rem & 127;                      // n fastest -> coalesced
    const float* W = (mat == 0) ? Wq : ((mat == 1) ? Wk : Wv);
    int q0[4], q1[4];
#pragma unroll
    for (int j = 0; j < 4; j++) {
        float w = W[(size_t)(kq * 4 + j) * FD + n];
        quant2(w, 256.f, 0.00390625f, q0[j], q1[j]);   // s0w = 2^-8
    }
    g_W8[((mat * 2 + 0) * 128 + n) * 32 + kq] = pack4(q0[0], q0[1], q0[2], q0[3]);
    g_W8[((mat * 2 + 1) * 128 + n) * 32 + kq] = pack4(q1[0], q1[1], q1[2], q1[3]);
}

// -------------------- int8 MMA GEMM: 3-term two-level --------------------
// 128x128x128 per block, 8 warps 4(m)x2(n), warp tile m32 x n64.
// Per ks (k32): 12 LDSM.x4 feed 48 s8 MMAs; only 4 ks steps.
// acc0 = X0*W0 (scale 2^-12); acc1 = X0*W1 + X1*W0 (shared scale 2^-20).
// 144-byte rows (36 u32) == 4 (mod 32): LDSM 8-row tiles conflict-free.
// B fragment pairing: ldmatrix tiles [0]=(nlo,klo) [1]=(nlo,khi) [2]=(nhi,klo)
// [3]=(nhi,khi); s8 mma takes (b0,b1) = (k<16, k>=16) of ONE n8 tile ->
// pairs (b[0],b[1]) and (b[2],b[3]).  (R14 bug: paired [0],[2] / [1],[3].)
#define XB0 0
#define XB1 4608
#define WB0 9216
#define WB1 13824
#define SMEM_U32 18432
#define SMEM_BYTES (SMEM_U32 * 4)   // 73728

__device__ __forceinline__ void mma_s8(int* c, const u32* a, u32 b0, u32 b1) {
    asm volatile(
        "mma.sync.aligned.m16n8k32.row.col.s32.s8.s8.s32 "
        "{%0,%1,%2,%3}, {%4,%5,%6,%7}, {%8,%9}, {%0,%1,%2,%3};"
        : "+r"(c[0]), "+r"(c[1]), "+r"(c[2]), "+r"(c[3])
        : "r"(a[0]), "r"(a[1]), "r"(a[2]), "r"(a[3]), "r"(b0), "r"(b1));
}
__device__ __forceinline__ void ldsm4(u32* r, u32 addr) {
    asm volatile("ldmatrix.sync.aligned.m8n8.x4.shared.b16 {%0,%1,%2,%3}, [%4];"
        : "=r"(r[0]), "=r"(r[1]), "=r"(r[2]), "=r"(r[3]) : "r"(addr));
}

__global__ __launch_bounds__(256) void gemm_mma_kernel(
    const float* __restrict__ x,
    const float* __restrict__ bq, const float* __restrict__ bk)
{
    extern __shared__ u32 sm[];
    const u32 sb   = smem_u32(sm);
    const int t    = threadIdx.x;
    const int warp = t >> 5;
    const int lane = t & 31;
    const int gID  = lane >> 2;
    const int tig  = lane & 3;
    const int row0 = blockIdx.x * 128;

    // ---- stage x tile: two-level int8 quantize ----
    {
        int r    = t >> 1;
        int half = t & 1;
        bool rok = (row0 + r) < NN;
        const float4* xr = (const float4*)(x + (size_t)(row0 + r) * FD + half * 64);
        int base = r * 36 + half * 16;
#pragma unroll
        for (int i = 0; i < 16; i++) {
            float4 v = rok ? xr[i] : make_float4(0.f, 0.f, 0.f, 0.f);
            int a0, a1, b0, b1, c0, c1, d0, d1;
            quant2(v.x, 16.f, 0.0625f, a0, a1);   // s0x = 2^-4
            quant2(v.y, 16.f, 0.0625f, b0, b1);
            quant2(v.z, 16.f, 0.0625f, c0, c1);
            quant2(v.w, 16.f, 0.0625f, d0, d1);
            sm[XB0 + base + i] = pack4(a0, b0, c0, d0);
            sm[XB1 + base + i] = pack4(a1, b1, c1, d1);
        }
    }

    // warp tiling: wm in [0,4) rows wm*32..+31, wn in [0,2) cols wn*64..+63
    const int wm = warp & 3;
    const int wn = warp >> 2;
    const int aLRow = (lane & 7) + 8 * ((lane >> 3) & 1);
    const u32 aColB = 16u * (lane >> 4);
    const int bLRow = (lane & 7) + 8 * (lane >> 4);
    const u32 bColB = 16u * ((lane >> 3) & 1);

    const u32 aBase00 = sb + 4u * (XB0 + (u32)(wm * 32 + aLRow) * 36u) + aColB;
    const u32 aBase01 = aBase00 + 4u * 16u * 36u;
    const u32 aBase10 = sb + 4u * (XB1 + (u32)(wm * 32 + aLRow) * 36u) + aColB;
    const u32 aBase11 = aBase10 + 4u * 16u * 36u;
    const u32 bOffRow = sb + 4u * (u32)(wn * 64 + bLRow) * 36u + bColB;

    for (int mat = 0; mat < 3; mat++) {
        __syncthreads();   // W buffers free (prev mainloop done); covers X stage on mat 0
        // stage W levels: 2 x 128 n x 32 u32 = 2048 uint4, 8 per thread
        {
#pragma unroll
            for (int j = 0; j < 8; j++) {
                int idx = j * 256 + t;
                int lvl = idx >> 10;
                int rem = idx & 1023;
                int n   = rem >> 3;
                int q4  = rem & 7;
                uint4 v = *(const uint4*)(g_W8 + ((size_t)(mat * 2 + lvl) * 128 + n) * 32 + q4 * 4);
                *(uint4*)(sm + (lvl ? WB1 : WB0) + n * 36 + q4 * 4) = v;
            }
        }
        __syncthreads();

        int acc0[2][8][4], acc1[2][8][4];
#pragma unroll
        for (int i = 0; i < 2; i++)
#pragma unroll
            for (int nt = 0; nt < 8; nt++)
#pragma unroll
                for (int c = 0; c < 4; c++) { acc0[i][nt][c] = 0; acc1[i][nt][c] = 0; }

#pragma unroll
        for (int ks = 0; ks < 4; ks++) {
            u32 a00[4], a01[4], a10[4], a11[4], bh0[4][4], bh1[4][4];
            ldsm4(a00, aBase00 + 32u * ks);
            ldsm4(a01, aBase01 + 32u * ks);
            ldsm4(a10, aBase10 + 32u * ks);
            ldsm4(a11, aBase11 + 32u * ks);
#pragma unroll
            for (int j = 0; j < 4; j++) {
                ldsm4(bh0[j], bOffRow + 4u * (WB0 + 16u * j * 36u) + 32u * ks);
                ldsm4(bh1[j], bOffRow + 4u * (WB1 + 16u * j * 36u) + 32u * ks);
            }
#pragma unroll
            for (int j = 0; j < 4; j++) {
                // X0*W0 -> acc0
                mma_s8(acc0[0][2 * j],     a00, bh0[j][0], bh0[j][1]);
                mma_s8(acc0[0][2 * j + 1], a00, bh0[j][2], bh0[j][3]);
                mma_s8(acc0[1][2 * j],     a01, bh0[j][0], bh0[j][1]);
                mma_s8(acc0[1][2 * j + 1], a01, bh0[j][2], bh0[j][3]);
                // X0*W1 -> acc1
                mma_s8(acc1[0][2 * j],     a00, bh1[j][0], bh1[j][1]);
                mma_s8(acc1[0][2 * j + 1], a00, bh1[j][2], bh1[j][3]);
                mma_s8(acc1[1][2 * j],     a01, bh1[j][0], bh1[j][1]);
                mma_s8(acc1[1][2 * j + 1], a01, bh1[j][2], bh1[j][3]);
                // X1*W0 -> acc1 (same scale 2^-20)
                mma_s8(acc1[0][2 * j],     a10, bh0[j][0], bh0[j][1]);
                mma_s8(acc1[0][2 * j + 1], a10, bh0[j][2], bh0[j][3]);
                mma_s8(acc1[1][2 * j],     a11, bh0[j][0], bh0[j][1]);
                mma_s8(acc1[1][2 * j + 1], a11, bh0[j][2], bh0[j][3]);
            }
        }

        // ---- epilogue: scale + bias + relu + store ----
        const float S0 = 0x1p-12f, S1 = 0x1p-20f;
        const float* B = (mat == 0) ? bq : ((mat == 1) ? bk : nullptr);
        float* C = (mat == 0) ? g_Q : ((mat == 1) ? g_K : g_V);
        const bool dorelu = (mat < 2);
#pragma unroll
        for (int i = 0; i < 2; i++) {
            int r0 = row0 + wm * 32 + i * 16 + gID;
            int r1 = r0 + 8;
#pragma unroll
            for (int nt = 0; nt < 8; nt++) {
                int col = wn * 64 + nt * 8 + 2 * tig;
                float2 bv = B ? *(const float2*)(B + col) : make_float2(0.f, 0.f);
                float o00 = (float)acc0[i][nt][0] * S0 + (float)acc1[i][nt][0] * S1 + bv.x;
                float o01 = (float)acc0[i][nt][1] * S0 + (float)acc1[i][nt][1] * S1 + bv.y;
                float o10 = (float)acc0[i][nt][2] * S0 + (float)acc1[i][nt][2] * S1 + bv.x;
                float o11 = (float)acc0[i][nt][3] * S0 + (float)acc1[i][nt][3] * S1 + bv.y;
                if (dorelu) {
                    o00 = fmaxf(o00, 0.f); o01 = fmaxf(o01, 0.f);
                    o10 = fmaxf(o10, 0.f); o11 = fmaxf(o11, 0.f);
                }
                if (r0 < NN) *(float2*)(C + (size_t)r0 * FD + col) = make_float2(o00, o01);
                if (r1 < NN) *(float2*)(C + (size_t)r1 * FD + col) = make_float2(o10, o11);
            }
        }
    }
}

// -------------------- fused attention + aggregation (1 warp / block) --------
__global__ __launch_bounds__(32) void aggregate_kernel(
    const float* __restrict__ bias, float* __restrict__ out)
{
    const int n    = blockIdx.x;
    const int lane = threadIdx.x;
    if (lane == 0) g_cnt[n] = 0;     // reset for next replay

    const float4 q = __ldg((const float4*)(g_Q + (size_t)n * FD + lane * 4));

    const int beg = g_off[n];
    const int end = g_off[n + 1];

    float m = -INFINITY;
    float s = 0.f;
    float4 acc = make_float4(0.f, 0.f, 0.f, 0.f);

    int e = beg;
    for (; e + 4 <= end; e += 4) {
        int c0 = g_scol[e];
        int c1 = g_scol[e + 1];
        int c2 = g_scol[e + 2];
        int c3 = g_scol[e + 3];
        const float4 k0 = __ldg((const float4*)(g_K + (size_t)c0 * FD + lane * 4));
        const float4 k1 = __ldg((const float4*)(g_K + (size_t)c1 * FD + lane * 4));
        const float4 k2 = __ldg((const float4*)(g_K + (size_t)c2 * FD + lane * 4));
        const float4 k3 = __ldg((const float4*)(g_K + (size_t)c3 * FD + lane * 4));
        const float4 v0 = __ldg((const float4*)(g_V + (size_t)c0 * FD + lane * 4));
        const float4 v1 = __ldg((const float4*)(g_V + (size_t)c1 * FD + lane * 4));
        const float4 v2 = __ldg((const float4*)(g_V + (size_t)c2 * FD + lane * 4));
        const float4 v3 = __ldg((const float4*)(g_V + (size_t)c3 * FD + lane * 4));

        float t0 = q.x * k0.x + q.y * k0.y + q.z * k0.z + q.w * k0.w;
        float t1 = q.x * k1.x + q.y * k1.y + q.z * k1.z + q.w * k1.w;
        float t2 = q.x * k2.x + q.y * k2.y + q.z * k2.z + q.w * k2.w;
        float t3 = q.x * k3.x + q.y * k3.y + q.z * k3.z + q.w * k3.w;
        t0 += __shfl_xor_sync(0xffffffffu, t0, 1);
        t1 += __shfl_xor_sync(0xffffffffu, t1, 1);
        t2 += __shfl_xor_sync(0xffffffffu, t2, 1);
        t3 += __shfl_xor_sync(0xffffffffu, t3, 1);
        t0 += __shfl_xor_sync(0xffffffffu, t0, 2);
        t1 += __shfl_xor_sync(0xffffffffu, t1, 2);
        t2 += __shfl_xor_sync(0xffffffffu, t2, 2);
        t3 += __shfl_xor_sync(0xffffffffu, t3, 2);

        float nm = fmaxf(fmaxf(m, fmaxf(t0, t1)), fmaxf(t2, t3));
        float f  = __expf(m - nm);
        float w0 = __expf(t0 - nm);
        float w1 = __expf(t1 - nm);
        float w2 = __expf(t2 - nm);
        float w3 = __expf(t3 - nm);
        s = s * f + ((w0 + w1) + (w2 + w3));
        acc.x = acc.x * f + ((w0 * v0.x + w1 * v1.x) + (w2 * v2.x + w3 * v3.x));
        acc.y = acc.y * f + ((w0 * v0.y + w1 * v1.y) + (w2 * v2.y + w3 * v3.y));
        acc.z = acc.z * f + ((w0 * v0.z + w1 * v1.z) + (w2 * v2.z + w3 * v3.z));
        acc.w = acc.w * f + ((w0 * v0.w + w1 * v1.w) + (w2 * v2.w + w3 * v3.w));
        m = nm;
    }
    for (; e < end; e++) {
        int c0 = g_scol[e];
        const float4 k0 = __ldg((const float4*)(g_K + (size_t)c0 * FD + lane * 4));
        const float4 v0 = __ldg((const float4*)(g_V + (size_t)c0 * FD + lane * 4));
        float t0 = q.x * k0.x + q.y * k0.y + q.z * k0.z + q.w * k0.w;
        t0 += __shfl_xor_sync(0xffffffffu, t0, 1);
        t0 += __shfl_xor_sync(0xffffffffu, t0, 2);
        float nm = fmaxf(m, t0);
        float f  = __expf(m - nm);
        float w0 = __expf(t0 - nm);
        s = s * f + w0;
        acc.x = acc.x * f + w0 * v0.x;
        acc.y = acc.y * f + w0 * v0.y;
        acc.z = acc.z * f + w0 * v0.z;
        acc.w = acc.w * f + w0 * v0.w;
        m = nm;
    }

    const float inv = 1.f / s;
    const float4 b4 = __ldg((const float4*)(bias + lane * 4));
    float4 o = make_float4(acc.x * inv + b4.x, acc.y * inv + b4.y,
                           acc.z * inv + b4.z, acc.w * inv + b4.w);
    *(float4*)(out + (size_t)n * FD + lane * 4) = o;
}

// -------------------- launch: fork sort chain alongside GEMM chain ----------
extern "C" void kernel_launch(void* const* d_in, const int* in_sizes, int n_in,
                              void* d_out, int out_size)
{
    const float* x  = (const float*)d_in[0];
    const int*   ei = (const int*)d_in[1];
    const float* Wq = (const float*)d_in[2];
    const float* bq = (const float*)d_in[3];
    const float* Wk = (const float*)d_in[4];
    const float* bk = (const float*)d_in[5];
    const float* Wv = (const float*)d_in[6];
    const float* bo = (const float*)d_in[7];
    float* out = (float*)d_out;

    static cudaStream_t s1;
    static cudaEvent_t  eFork, eJoin;
    static int inited = 0;
    if (!inited) {
        cudaStreamCreateWithFlags(&s1, cudaStreamNonBlocking);
        cudaEventCreateWithFlags(&eFork, cudaEventDisableTiming);
        cudaEventCreateWithFlags(&eJoin, cudaEventDisableTiming);
        cudaFuncSetAttribute(gemm_mma_kernel,
                             cudaFuncAttributeMaxDynamicSharedMemorySize, SMEM_BYTES);
        inited = 1;
    }

    // fork: sort chain on s1
    cudaEventRecord(eFork, 0);
    cudaStreamWaitEvent(s1, eFork, 0);
    hist_kernel<<<HIST_BLOCKS, 256, 0, s1>>>(ei);
    scan_kernel<<<1, 1024, 0, s1>>>();
    scatter_kernel<<<(EP + 255) / 256, 256, 0, s1>>>(ei);
    cudaEventRecord(eJoin, s1);

    // main stream: GEMM chain (overlaps the sort chain)
    prep_kernel<<<PREP_BLOCKS, 256>>>(Wq, Wk, Wv);
    gemm_mma_kernel<<<GEMM_BX, 256, SMEM_BYTES>>>(x, bq, bk);

    // join, then aggregate (one warp per block -> no intra-block tail)
    cudaStreamWaitEvent(0, eJoin, 0);
    aggregate_kernel<<<NN, 32>>>(bo, out);
}

// round 17
// speedup vs baseline: 1.0341x; 1.0341x over previous
#include <cuda_runtime.h>
#include <cuda_bf16.h>
#include <math.h>
#include <stdint.h>

#define NN 50000
#define NE 800000
#define EP (NE + NN)   // edges + self loops
#define FD 128

#define HIST_BLOCKS ((NE + 255) / 256)   // 3125
#define PREP_BLOCKS 24
#define GEMM_BX     ((NN + 127) / 128)   // 391

typedef uint32_t u32;

// -------------------- device scratch (no allocs allowed) --------------------
__device__ float  g_Q[NN * FD];
__device__ float  g_K[NN * FD];
__device__ float  g_V[NN * FD];
__device__ int    g_cnt[NN];     // zeroed at load; re-zeroed by score each replay
__device__ int    g_off[NN + 1];
__device__ int    g_cur[NN];
__device__ int    g_scol[EP];
__device__ float  g_sc[EP * 8];      // raw per-head scores (edge-major)
__device__ float2 g_ms[NN * 8];      // (max, 1/sum) per node per head  [R16 bug: was NN]
// W transposed (N-major) + bf16-split: [mat][part(hi/lo)][n=128][kpair=64] u32
__device__ u32    g_Wt[3 * 2 * 128 * 64];

// -------------------- bf16 split helpers (RN-even) --------------------
__device__ __forceinline__ u32 f2bf(float x) {
    u32 u = __float_as_uint(x);
    return (u + 0x7FFFu + ((u >> 16) & 1u)) >> 16;
}
__device__ __forceinline__ float bf2f(u32 b) { return __uint_as_float(b << 16); }

__device__ __forceinline__ u32 smem_u32(const void* p) {
    u32 a; asm("{ .reg .u64 t; cvta.to.shared.u64 t, %1; cvt.u32.u64 %0, t; }"
               : "=r"(a) : "l"(p));
    return a;
}

// -------------------- sort chain (secondary stream) --------------------
__global__ void hist_kernel(const int* __restrict__ ei) {
    int e = blockIdx.x * blockDim.x + threadIdx.x;
    if (e < NE) atomicAdd(&g_cnt[ei[e]], 1);   // target = ei[0][e]
}

// exclusive scan over (g_cnt[i] + 1); +1 = implicit self loop
__global__ __launch_bounds__(1024) void scan_kernel() {
    __shared__ int sums[1024];
    const int t = threadIdx.x;
    const int CH = (NN + 1023) / 1024;   // 49
    int start = t * CH;
    int end   = start + CH; if (end > NN) end = NN;

    int s = 0;
    for (int i = start; i < end; i++) s += g_cnt[i] + 1;
    sums[t] = s;
    __syncthreads();
    for (int d = 1; d < 1024; d <<= 1) {
        int v = (t >= d) ? sums[t - d] : 0;
        __syncthreads();
        sums[t] += v;
        __syncthreads();
    }
    int run = sums[t] - s;
    for (int i = start; i < end; i++) {
        g_off[i] = run;
        g_cur[i] = run;
        run += g_cnt[i] + 1;
    }
    if (start < NN && end == NN) g_off[NN] = run;
}

__global__ void scatter_kernel(const int* __restrict__ ei) {
    int e = blockIdx.x * blockDim.x + threadIdx.x;
    if (e >= EP) return;
    int rr, cc;
    if (e < NE) { rr = ei[e]; cc = ei[NE + e]; }
    else        { rr = e - NE; cc = rr; }          // self loop
    int pos = atomicAdd(&g_cur[rr], 1);
    g_scol[pos] = cc;
}

// -------------------- W prep (main stream, before gemm) --------------------
__global__ __launch_bounds__(256) void prep_kernel(
    const float* __restrict__ Wq, const float* __restrict__ Wk,
    const float* __restrict__ Wv)
{
    int gid = blockIdx.x * 256 + threadIdx.x;   // 0..6143
#pragma unroll
    for (int i = 0; i < 4; i++) {
        int P   = gid + i * 6144;            // 0..24575
        int mat = P >> 13;
        int kp  = (P >> 7) & 63;
        int n   = P & 127;                   // n fastest -> coalesced W reads
        const float* W = (mat == 0) ? Wq : ((mat == 1) ? Wk : Wv);
        float w0 = W[(2 * kp) * FD + n];
        float w1 = W[(2 * kp + 1) * FD + n];
        u32 h0 = f2bf(w0), h1 = f2bf(w1);
        u32 l0 = f2bf(w0 - bf2f(h0)), l1 = f2bf(w1 - bf2f(h1));
        g_Wt[((mat * 2 + 0) * 128 + n) * 64 + kp] = h0 | (h1 << 16);
        g_Wt[((mat * 2 + 1) * 128 + n) * 64 + kp] = l0 | (l1 << 16);
    }
}

// -------------------- HMMA GEMM (R13 body, mat range parameterized) ---------
#define XH 0
#define XL 8704
#define WH 17408
#define WL 26112
#define SMEM_BYTES (34816 * 4)   // 139264

__device__ __forceinline__ void mma_bf16(float* c, const u32* a, u32 b0, u32 b1) {
    asm volatile(
        "mma.sync.aligned.m16n8k16.row.col.f32.bf16.bf16.f32 "
        "{%0,%1,%2,%3}, {%4,%5,%6,%7}, {%8,%9}, {%0,%1,%2,%3};"
        : "+f"(c[0]), "+f"(c[1]), "+f"(c[2]), "+f"(c[3])
        : "r"(a[0]), "r"(a[1]), "r"(a[2]), "r"(a[3]), "r"(b0), "r"(b1));
}
__device__ __forceinline__ void ldsm4(u32* r, u32 addr) {
    asm volatile("ldmatrix.sync.aligned.m8n8.x4.shared.b16 {%0,%1,%2,%3}, [%4];"
        : "=r"(r[0]), "=r"(r[1]), "=r"(r[2]), "=r"(r[3]) : "r"(addr));
}

__global__ __launch_bounds__(256) void gemm_mma_kernel(
    const float* __restrict__ x,
    const float* __restrict__ bq, const float* __restrict__ bk,
    int m0, int m1)
{
    extern __shared__ u32 sm[];
    const u32 sb   = smem_u32(sm);
    const int t    = threadIdx.x;
    const int warp = t >> 5;
    const int lane = t & 31;
    const int gID  = lane >> 2;
    const int tig  = lane & 3;
    const int row0 = blockIdx.x * 128;

    // ---- stage x tile: split into bf16 hi/lo ----
    {
        int r    = t >> 1;
        int half = t & 1;
        bool rok = (row0 + r) < NN;
        const float4* xr = (const float4*)(x + (size_t)(row0 + r) * FD + half * 64);
        int base = r * 68 + half * 32;
#pragma unroll
        for (int i = 0; i < 16; i++) {
            float4 v = rok ? xr[i] : make_float4(0.f, 0.f, 0.f, 0.f);
            u32 hx = f2bf(v.x), hy = f2bf(v.y), hz = f2bf(v.z), hw = f2bf(v.w);
            u32 lx = f2bf(v.x - bf2f(hx)), ly = f2bf(v.y - bf2f(hy));
            u32 lz = f2bf(v.z - bf2f(hz)), lw = f2bf(v.w - bf2f(hw));
            sm[XH + base + 2 * i]     = hx | (hy << 16);
            sm[XH + base + 2 * i + 1] = hz | (hw << 16);
            sm[XL + base + 2 * i]     = lx | (ly << 16);
            sm[XL + base + 2 * i + 1] = lz | (lw << 16);
        }
    }

    const int wm = warp & 3;
    const int wn = warp >> 2;
    const int aLRow = (lane & 7) + 8 * ((lane >> 3) & 1);
    const u32 aColB = 16u * (lane >> 4);
    const int bLRow = (lane & 7) + 8 * (lane >> 4);
    const u32 bColB = 16u * ((lane >> 3) & 1);

    const u32 aBaseH0 = sb + 4u * (XH + (u32)(wm * 32 + aLRow) * 68u) + aColB;
    const u32 aBaseH1 = aBaseH0 + 4u * 16u * 68u;
    const u32 aBaseL0 = sb + 4u * (XL + (u32)(wm * 32 + aLRow) * 68u) + aColB;
    const u32 aBaseL1 = aBaseL0 + 4u * 16u * 68u;
    const u32 bOffRow = sb + 4u * (u32)(wn * 64 + bLRow) * 68u + bColB;

    for (int mat = m0; mat < m1; mat++) {
        __syncthreads();   // W buffers free; covers X stage on first mat
        {
            int part = t >> 7;
            int n    = t & 127;
            const uint4* src = (const uint4*)(g_Wt + ((mat * 2 + part) * 128 + n) * 64);
            u32* dst = sm + (part ? WL : WH) + n * 68;
#pragma unroll
            for (int j = 0; j < 16; j++)
                *(uint4*)(dst + 4 * j) = src[j];
        }
        __syncthreads();

        float acc[2][8][4];
#pragma unroll
        for (int i = 0; i < 2; i++)
#pragma unroll
            for (int nt = 0; nt < 8; nt++)
#pragma unroll
                for (int c = 0; c < 4; c++) acc[i][nt][c] = 0.f;

#pragma unroll
        for (int ks = 0; ks < 8; ks++) {
            u32 ah0[4], ah1[4], al0[4], al1[4], bh[4][4], bl[4][4];
            ldsm4(ah0, aBaseH0 + 32u * ks);
            ldsm4(ah1, aBaseH1 + 32u * ks);
            ldsm4(al0, aBaseL0 + 32u * ks);
            ldsm4(al1, aBaseL1 + 32u * ks);
#pragma unroll
            for (int j = 0; j < 4; j++) {
                ldsm4(bh[j], bOffRow + 4u * (WH + 16u * j * 68u) + 32u * ks);
                ldsm4(bl[j], bOffRow + 4u * (WL + 16u * j * 68u) + 32u * ks);
            }
#pragma unroll
            for (int j = 0; j < 4; j++) {
                mma_bf16(acc[0][2 * j],     ah0, bh[j][0], bh[j][1]);
                mma_bf16(acc[0][2 * j + 1], ah0, bh[j][2], bh[j][3]);
                mma_bf16(acc[1][2 * j],     ah1, bh[j][0], bh[j][1]);
                mma_bf16(acc[1][2 * j + 1], ah1, bh[j][2], bh[j][3]);
                mma_bf16(acc[0][2 * j],     al0, bh[j][0], bh[j][1]);
                mma_bf16(acc[0][2 * j + 1], al0, bh[j][2], bh[j][3]);
                mma_bf16(acc[1][2 * j],     al1, bh[j][0], bh[j][1]);
                mma_bf16(acc[1][2 * j + 1], al1, bh[j][2], bh[j][3]);
                mma_bf16(acc[0][2 * j],     ah0, bl[j][0], bl[j][1]);
                mma_bf16(acc[0][2 * j + 1], ah0, bl[j][2], bl[j][3]);
                mma_bf16(acc[1][2 * j],     ah1, bl[j][0], bl[j][1]);
                mma_bf16(acc[1][2 * j + 1], ah1, bl[j][2], bl[j][3]);
            }
        }

        const float* B = (mat == 0) ? bq : ((mat == 1) ? bk : nullptr);
        float* C = (mat == 0) ? g_Q : ((mat == 1) ? g_K : g_V);
        const bool dorelu = (mat < 2);
#pragma unroll
        for (int i = 0; i < 2; i++) {
            int r0 = row0 + wm * 32 + i * 16 + gID;
            int r1 = r0 + 8;
#pragma unroll
            for (int nt = 0; nt < 8; nt++) {
                int col = wn * 64 + nt * 8 + 2 * tig;
                float2 bv = B ? *(const float2*)(B + col) : make_float2(0.f, 0.f);
                float2 o0 = make_float2(acc[i][nt][0] + bv.x, acc[i][nt][1] + bv.y);
                float2 o1 = make_float2(acc[i][nt][2] + bv.x, acc[i][nt][3] + bv.y);
                if (dorelu) {
                    o0.x = fmaxf(o0.x, 0.f); o0.y = fmaxf(o0.y, 0.f);
                    o1.x = fmaxf(o1.x, 0.f); o1.y = fmaxf(o1.y, 0.f);
                }
                if (r0 < NN) *(float2*)(C + (size_t)r0 * FD + col) = o0;
                if (r1 < NN) *(float2*)(C + (size_t)r1 * FD + col) = o1;
            }
        }
    }
}

// -------------------- phase 1: scores + softmax stats (needs Q,K only) ------
__global__ __launch_bounds__(32) void score_kernel() {
    const int n    = blockIdx.x;
    const int lane = threadIdx.x;
    if (lane == 0) g_cnt[n] = 0;     // reset for next replay

    const float4 q = __ldg((const float4*)(g_Q + (size_t)n * FD + lane * 4));
    const int beg = g_off[n];
    const int end = g_off[n + 1];
    const int h   = lane >> 2;       // head this lane's 4 dims belong to
    const bool wr = (lane & 3) == 0; // one writer per head group

    float m = -INFINITY;
    float s = 0.f;

    int e = beg;
    for (; e + 4 <= end; e += 4) {
        int c0 = g_scol[e];
        int c1 = g_scol[e + 1];
        int c2 = g_scol[e + 2];
        int c3 = g_scol[e + 3];
        const float4 k0 = __ldg((const float4*)(g_K + (size_t)c0 * FD + lane * 4));
        const float4 k1 = __ldg((const float4*)(g_K + (size_t)c1 * FD + lane * 4));
        const float4 k2 = __ldg((const float4*)(g_K + (size_t)c2 * FD + lane * 4));
        const float4 k3 = __ldg((const float4*)(g_K + (size_t)c3 * FD + lane * 4));

        float t0 = q.x * k0.x + q.y * k0.y + q.z * k0.z + q.w * k0.w;
        float t1 = q.x * k1.x + q.y * k1.y + q.z * k1.z + q.w * k1.w;
        float t2 = q.x * k2.x + q.y * k2.y + q.z * k2.z + q.w * k2.w;
        float t3 = q.x * k3.x + q.y * k3.y + q.z * k3.z + q.w * k3.w;
        t0 += __shfl_xor_sync(0xffffffffu, t0, 1);
        t1 += __shfl_xor_sync(0xffffffffu, t1, 1);
        t2 += __shfl_xor_sync(0xffffffffu, t2, 1);
        t3 += __shfl_xor_sync(0xffffffffu, t3, 1);
        t0 += __shfl_xor_sync(0xffffffffu, t0, 2);
        t1 += __shfl_xor_sync(0xffffffffu, t1, 2);
        t2 += __shfl_xor_sync(0xffffffffu, t2, 2);
        t3 += __shfl_xor_sync(0xffffffffu, t3, 2);

        if (wr) {
            g_sc[(size_t)(e)     * 8 + h] = t0;
            g_sc[(size_t)(e + 1) * 8 + h] = t1;
            g_sc[(size_t)(e + 2) * 8 + h] = t2;
            g_sc[(size_t)(e + 3) * 8 + h] = t3;
        }

        float nm = fmaxf(fmaxf(m, fmaxf(t0, t1)), fmaxf(t2, t3));
        float f  = __expf(m - nm);
        s = s * f + ((__expf(t0 - nm) + __expf(t1 - nm)) +
                     (__expf(t2 - nm) + __expf(t3 - nm)));
        m = nm;
    }
    for (; e < end; e++) {
        int c0 = g_scol[e];
        const float4 k0 = __ldg((const float4*)(g_K + (size_t)c0 * FD + lane * 4));
        float t0 = q.x * k0.x + q.y * k0.y + q.z * k0.z + q.w * k0.w;
        t0 += __shfl_xor_sync(0xffffffffu, t0, 1);
        t0 += __shfl_xor_sync(0xffffffffu, t0, 2);
        if (wr) g_sc[(size_t)e * 8 + h] = t0;
        float nm = fmaxf(m, t0);
        float f  = __expf(m - nm);
        s = s * f + __expf(t0 - nm);
        m = nm;
    }

    // each head group's lanes hold identical (m, s); one writer per head
    if (wr) g_ms[(size_t)n * 8 + h] = make_float2(m, 1.f / s);
}

// -------------------- phase 2: apply weights to V ---------------------------
__global__ __launch_bounds__(32) void applyV_kernel(
    const float* __restrict__ bias, float* __restrict__ out)
{
    const int n    = blockIdx.x;
    const int lane = threadIdx.x;
    const int h    = lane >> 2;
    const float2 ms = __ldg((const float2*)&g_ms[(size_t)n * 8 + h]);
    const float m = ms.x, inv = ms.y;

    const int beg = g_off[n];
    const int end = g_off[n + 1];

    float4 acc = make_float4(0.f, 0.f, 0.f, 0.f);

    int e = beg;
    for (; e + 4 <= end; e += 4) {
        int c0 = g_scol[e];
        int c1 = g_scol[e + 1];
        int c2 = g_scol[e + 2];
        int c3 = g_scol[e + 3];
        float t0 = __ldg(&g_sc[(size_t)(e)     * 8 + h]);
        float t1 = __ldg(&g_sc[(size_t)(e + 1) * 8 + h]);
        float t2 = __ldg(&g_sc[(size_t)(e + 2) * 8 + h]);
        float t3 = __ldg(&g_sc[(size_t)(e + 3) * 8 + h]);
        const float4 v0 = __ldg((const float4*)(g_V + (size_t)c0 * FD + lane * 4));
        const float4 v1 = __ldg((const float4*)(g_V + (size_t)c1 * FD + lane * 4));
        const float4 v2 = __ldg((const float4*)(g_V + (size_t)c2 * FD + lane * 4));
        const float4 v3 = __ldg((const float4*)(g_V + (size_t)c3 * FD + lane * 4));

        float w0 = __expf(t0 - m);
        float w1 = __expf(t1 - m);
        float w2 = __expf(t2 - m);
        float w3 = __expf(t3 - m);
        acc.x += (w0 * v0.x + w1 * v1.x) + (w2 * v2.x + w3 * v3.x);
        acc.y += (w0 * v0.y + w1 * v1.y) + (w2 * v2.y + w3 * v3.y);
        acc.z += (w0 * v0.z + w1 * v1.z) + (w2 * v2.z + w3 * v3.z);
        acc.w += (w0 * v0.w + w1 * v1.w) + (w2 * v2.w + w3 * v3.w);
    }
    for (; e < end; e++) {
        int c0 = g_scol[e];
        float t0 = __ldg(&g_sc[(size_t)e * 8 + h]);
        const float4 v0 = __ldg((const float4*)(g_V + (size_t)c0 * FD + lane * 4));
        float w0 = __expf(t0 - m);
        acc.x += w0 * v0.x;
        acc.y += w0 * v0.y;
        acc.z += w0 * v0.z;
        acc.w += w0 * v0.w;
    }

    const float4 b4 = __ldg((const float4*)(bias + lane * 4));
    float4 o = make_float4(acc.x * inv + b4.x, acc.y * inv + b4.y,
                           acc.z * inv + b4.z, acc.w * inv + b4.w);
    *(float4*)(out + (size_t)n * FD + lane * 4) = o;
}

// -------------------- launch: pipelined phases + forked sort chain ----------
extern "C" void kernel_launch(void* const* d_in, const int* in_sizes, int n_in,
                              void* d_out, int out_size)
{
    const float* x  = (const float*)d_in[0];
    const int*   ei = (const int*)d_in[1];
    const float* Wq = (const float*)d_in[2];
    const float* bq = (const float*)d_in[3];
    const float* Wk = (const float*)d_in[4];
    const float* bk = (const float*)d_in[5];
    const float* Wv = (const float*)d_in[6];
    const float* bo = (const float*)d_in[7];
    float* out = (float*)d_out;

    static cudaStream_t s1;
    static cudaEvent_t  eFork, eQK, eSc;
    static int inited = 0;
    if (!inited) {
        cudaStreamCreateWithFlags(&s1, cudaStreamNonBlocking);
        cudaEventCreateWithFlags(&eFork, cudaEventDisableTiming);
        cudaEventCreateWithFlags(&eQK,   cudaEventDisableTiming);
        cudaEventCreateWithFlags(&eSc,   cudaEventDisableTiming);
        cudaFuncSetAttribute(gemm_mma_kernel,
                             cudaFuncAttributeMaxDynamicSharedMemorySize, SMEM_BYTES);
        inited = 1;
    }

    // fork: sort chain on s1
    cudaEventRecord(eFork, 0);
    cudaStreamWaitEvent(s1, eFork, 0);
    hist_kernel<<<HIST_BLOCKS, 256, 0, s1>>>(ei);
    scan_kernel<<<1, 1024, 0, s1>>>();
    scatter_kernel<<<(EP + 255) / 256, 256, 0, s1>>>(ei);

    // main: prep + Q/K GEMM
    prep_kernel<<<PREP_BLOCKS, 256>>>(Wq, Wk, Wv);
    gemm_mma_kernel<<<GEMM_BX, 256, SMEM_BYTES>>>(x, bq, bk, 0, 2);
    cudaEventRecord(eQK, 0);

    // s1: scores (needs sort [in-order] + Q/K) — overlaps V GEMM on main
    cudaStreamWaitEvent(s1, eQK, 0);
    score_kernel<<<NN, 32, 0, s1>>>();
    cudaEventRecord(eSc, s1);

    // main: V GEMM, then apply weights
    gemm_mma_kernel<<<GEMM_BX, 256, SMEM_BYTES>>>(x, bq, bk, 2, 3);
    cudaStreamWaitEvent(0, eSc, 0);
    applyV_kernel<<<NN, 32>>>(bo, out);
}